// round 10
// baseline (speedup 1.0000x reference)
#include <cuda_runtime.h>
#include <cuda_fp16.h>
#include <cstdint>
#include <math.h>

#define DN 16384
#define DL 10
#define DD 256

// ======================= helpers =======================

__device__ __forceinline__ uint32_t smem_u32(const void* p) {
    uint32_t a;
    asm("{ .reg .u64 t; cvta.to.shared.u64 t, %1; cvt.u32.u64 %0, t; }" : "=r"(a) : "l"(p));
    return a;
}

__device__ __forceinline__ void ldsm4(uint32_t* r, uint32_t a) {
    asm volatile("ldmatrix.sync.aligned.m8n8.x4.shared.b16 {%0,%1,%2,%3}, [%4];"
                 : "=r"(r[0]), "=r"(r[1]), "=r"(r[2]), "=r"(r[3]) : "r"(a));
}

__device__ __forceinline__ void mma16816(float* c, const uint32_t* a, uint32_t b0, uint32_t b1) {
    asm volatile("mma.sync.aligned.m16n8k16.row.col.f32.f16.f16.f32 "
                 "{%0,%1,%2,%3}, {%4,%5,%6,%7}, {%8,%9}, {%0,%1,%2,%3};"
                 : "+f"(c[0]), "+f"(c[1]), "+f"(c[2]), "+f"(c[3])
                 : "r"(a[0]), "r"(a[1]), "r"(a[2]), "r"(a[3]), "r"(b0), "r"(b1));
}

__device__ __forceinline__ void cp16(uint32_t s, const void* g) {
    asm volatile("cp.async.cg.shared.global [%0], [%1], 16;" :: "r"(s), "l"(g) : "memory");
}

// ======================= globals (scratch) =======================

__device__ __align__(16) float g_r[2 * DD];
__device__ __align__(16) float g_bo[DD];

__device__ __align__(16) __half g_Gt[2 * DD * DD];   // [512][256] (n-major, k contig)
__device__ __align__(16) __half g_Wt[DD * 2 * DD];   // [256][512]
__device__ __align__(16) __half g_M[(size_t)DN * DD];        // m_last fp16

// ======================= fused precompute =======================

__global__ void __launch_bounds__(256) prep(
    const float* __restrict__ w_in, const float* __restrict__ b_in,
    const float* __restrict__ w_out, const float* __restrict__ b_out,
    const float* __restrict__ msgs)
{
    __shared__ float sbuf[128 * 4];
    const int b = blockIdx.x;
    const int t = threadIdx.x;

    if (b < 128) {
        const int k0 = b * 4;
        const int h  = k0 >> 8;
        const int d0 = k0 & 255;
        {
            int j = t >> 1, half = t & 1;
            const float* wk = w_in + (size_t)(DD + h * 128 + j) * DD + d0 + half * 2;
            sbuf[j * 4 + half * 2]     = wk[0];
            sbuf[j * 4 + half * 2 + 1] = wk[1];
        }
        __syncthreads();
        const int e = t;
        float a0 = 0.f, a1 = 0.f, a2 = 0.f, a3 = 0.f;
        const float* wq = w_in + (size_t)(h * 128) * DD + e;
#pragma unroll 4
        for (int j = 0; j < 128; j++) {
            float q = wq[(size_t)j * DD];
            a0 = fmaf(q, sbuf[j * 4 + 0], a0);
            a1 = fmaf(q, sbuf[j * 4 + 1], a1);
            a2 = fmaf(q, sbuf[j * 4 + 2], a2);
            a3 = fmaf(q, sbuf[j * 4 + 3], a3);
        }
        g_Gt[(size_t)(k0 + 0) * DD + e] = __float2half_rn(a0);
        g_Gt[(size_t)(k0 + 1) * DD + e] = __float2half_rn(a1);
        g_Gt[(size_t)(k0 + 2) * DD + e] = __float2half_rn(a2);
        g_Gt[(size_t)(k0 + 3) * DD + e] = __float2half_rn(a3);
    } else if (b < 384) {
        const int d = b - 128;
        if (t < DD) sbuf[t] = w_out[(size_t)d * DD + t];
        __syncthreads();
#pragma unroll
        for (int rep = 0; rep < 2; rep++) {
            int k = t + rep * 256;
            int h = k >> 8, e = k & 255;
            const float* wv  = w_in + (size_t)(2 * DD + h * 128) * DD + e;
            const float* wor = sbuf + h * 128;
            float acc = 0.f;
#pragma unroll 8
            for (int j = 0; j < 128; j++)
                acc = fmaf(wor[j], wv[(size_t)j * DD], acc);
            g_Wt[(size_t)d * 512 + k] = __float2half_rn(acc);
        }
    } else if (b < 387) {
        int sb = b - 384;
        if (sb < 2) {
            int h = sb, d = t;
            float a = 0.f;
            for (int j = 0; j < 128; j++)
                a = fmaf(w_in[(size_t)(DD + h * 128 + j) * DD + d], b_in[h * 128 + j], a);
            g_r[h * DD + d] = a;
        } else {
            float a = b_out[t];
            for (int c = 0; c < DD; c++)
                a = fmaf(w_out[(size_t)t * DD + c], b_in[2 * DD + c], a);
            g_bo[t] = a;
        }
    } else {
        int idx = (b - 387) * 256 + t;
        int n = idx >> 6, d4 = (idx & 63) * 4;
        float4 v = *reinterpret_cast<const float4*>(&msgs[((size_t)n * DL + (DL - 1)) * DD + d4]);
        __half2 p0 = __floats2half2_rn(v.x, v.y);
        __half2 p1 = __floats2half2_rn(v.z, v.w);
        *reinterpret_cast<__half2*>(&g_M[(size_t)n * DD + d4])     = p0;
        *reinterpret_cast<__half2*>(&g_M[(size_t)n * DD + d4 + 2]) = p1;
    }
}

// ======================= mega kernel =======================
// Per CTA (512 thr, 16 warps): 128 sequences.
//  P1: U[128x512] = M[128x256] @ Gt^T   (2 N-halves, warp 64x32, k-chunk 32, 3 stages)
//  P2: scores/softmax + Mb aggregation (U,Mb in smem)
//  P3: OUT[128x256] = Mb[128x512] @ Wt^T (A from smem, B staged)

#define U_PITCH   1040
#define U_BYTES   (128 * U_PITCH)            // 133120
#define P1_ABUF   (128 * 80)                 // 10240
#define P1_STG    (P1_ABUF + 256 * 80)       // 30720
#define P3_STG    (256 * 80)                 // 20480
#define MEGA_SMEM (U_BYTES + 3 * P1_STG)     // 225280

__global__ void __launch_bounds__(512, 1) mega(
    const float* __restrict__ msgs, const float* __restrict__ tstamp,
    const float* __restrict__ w_time, const float* __restrict__ b_time,
    const int* __restrict__ lengths, float* __restrict__ out)
{
    extern __shared__ char sm[];
    const int tid = threadIdx.x, lane = tid & 31, wid = tid >> 5;
    const int m0 = blockIdx.x * 128;
    const uint32_t uU   = smem_u32(sm);
    const uint32_t uStg = uU + U_BYTES;

    const int wm = (wid >> 3) * 64;      // 2 m-groups of 64
    const int wn = (wid & 7) * 32;       // 8 n-groups of 32

    // ---------- phase 1 ----------
#define P1_LOAD(st, k0c) do { \
        uint32_t s0 = uStg + (st) * P1_STG; \
        _Pragma("unroll") \
        for (int it = 0; it < 3; it++) { \
            int idx = tid + it * 512; \
            if (idx < 512) { \
                int r = idx >> 2, q = idx & 3; \
                cp16(s0 + r * 80 + q * 16, g_M + (size_t)(m0 + r) * 256 + (k0c) + q * 8); \
            } else { \
                int j = idx - 512, r = j >> 2, q = j & 3; \
                cp16(s0 + P1_ABUF + r * 80 + q * 16, g_Gt + (size_t)(nb + r) * 256 + (k0c) + q * 8); \
            } \
        } \
        asm volatile("cp.async.commit_group;" ::: "memory"); \
    } while (0)

#define P3_LOAD(st, k0c) do { \
        uint32_t s0 = uStg + (st) * P3_STG; \
        _Pragma("unroll") \
        for (int it = 0; it < 2; it++) { \
            int idx = tid + it * 512; \
            int r = idx >> 2, q = idx & 3; \
            cp16(s0 + r * 80 + q * 16, g_Wt + (size_t)r * 512 + (k0c) + q * 8); \
        } \
        asm volatile("cp.async.commit_group;" ::: "memory"); \
    } while (0)

#pragma unroll 1
    for (int half = 0; half < 2; half++) {
        const int nb = half * 256;
        float acc[4][4][4];
#pragma unroll
        for (int a = 0; a < 4; a++)
#pragma unroll
            for (int bq = 0; bq < 4; bq++)
#pragma unroll
                for (int cc = 0; cc < 4; cc++) acc[a][bq][cc] = 0.f;

        P1_LOAD(0, 0);
        P1_LOAD(1, 32);
#pragma unroll 1
        for (int c = 0; c < 8; c++) {
            asm volatile("cp.async.wait_group 1;" ::: "memory");
            __syncthreads();
            if (c + 2 < 8) { P1_LOAD((c + 2) % 3, (c + 2) * 32); }
            else { asm volatile("cp.async.commit_group;" ::: "memory"); }

            const uint32_t uA = uStg + (c % 3) * P1_STG;
            const uint32_t uB = uA + P1_ABUF;
#pragma unroll
            for (int kk = 0; kk < 2; kk++) {
                const uint32_t colb = (uint32_t)(kk * 32 + (lane >> 4) * 16);
                const uint32_t arow = (uint32_t)(wm + (lane & 15));
                uint32_t af[4][4], bf[2][4];
#pragma unroll
                for (int nt = 0; nt < 2; nt++) {
                    uint32_t brow = (uint32_t)(wn + nt * 16 + (lane & 15));
                    ldsm4(bf[nt], uB + brow * 80 + colb);
                }
#pragma unroll
                for (int mt = 0; mt < 4; mt++)
                    ldsm4(af[mt], uA + (arow + mt * 16) * 80 + colb);
#pragma unroll
                for (int mt = 0; mt < 4; mt++)
#pragma unroll
                    for (int ns = 0; ns < 4; ns++)
                        mma16816(acc[mt][ns], af[mt], bf[ns >> 1][ns & 1], bf[ns >> 1][(ns & 1) + 2]);
            }
        }
        asm volatile("cp.async.wait_group 0;" ::: "memory");
        __syncthreads();

        // prefetch phase-3 B stages early (overlaps epilogue + phase 2)
        if (half == 1) { P3_LOAD(0, 0); P3_LOAD(1, 32); }

        // epilogue: acc + g_r -> U smem (fp16)
#pragma unroll
        for (int mt = 0; mt < 4; mt++) {
            int r0 = wm + mt * 16 + (lane >> 2);
#pragma unroll
            for (int ns = 0; ns < 4; ns++) {
                int cx = nb + wn + ns * 8 + (lane & 3) * 2;
                float2 rr = *reinterpret_cast<const float2*>(g_r + cx);
                *reinterpret_cast<__half2*>(sm + (size_t)r0 * U_PITCH + cx * 2) =
                    __floats2half2_rn(acc[mt][ns][0] + rr.x, acc[mt][ns][1] + rr.y);
                *reinterpret_cast<__half2*>(sm + (size_t)(r0 + 8) * U_PITCH + cx * 2) =
                    __floats2half2_rn(acc[mt][ns][2] + rr.x, acc[mt][ns][3] + rr.y);
            }
        }
    }
    __syncthreads();   // U visible to all warps

    // ---------- phase 2: scores + softmax + aggregate (8 seqs per warp) ----------
    {
        const int e8 = lane * 8;
        float wt[8], bt[8];
        {
            float4 wa = *reinterpret_cast<const float4*>(w_time + e8);
            float4 wb = *reinterpret_cast<const float4*>(w_time + e8 + 4);
            float4 ba = *reinterpret_cast<const float4*>(b_time + e8);
            float4 bb = *reinterpret_cast<const float4*>(b_time + e8 + 4);
            wt[0]=wa.x; wt[1]=wa.y; wt[2]=wa.z; wt[3]=wa.w;
            wt[4]=wb.x; wt[5]=wb.y; wt[6]=wb.z; wt[7]=wb.w;
            bt[0]=ba.x; bt[1]=ba.y; bt[2]=ba.z; bt[3]=ba.w;
            bt[4]=bb.x; bt[5]=bb.y; bt[6]=bb.z; bt[7]=bb.w;
        }
        const float scale = 0.08838834764831845f;

#pragma unroll 1
        for (int i = 0; i < 8; i++) {
            const int s_loc = wid * 8 + i;
            const int s = m0 + s_loc;
            const int pad = DL - (lengths[s] + 1);

            float u0[8], u1[8];
            {
                uint4 h0 = *reinterpret_cast<const uint4*>(sm + (size_t)s_loc * U_PITCH + e8 * 2);
                uint4 h1 = *reinterpret_cast<const uint4*>(sm + (size_t)s_loc * U_PITCH + 512 + e8 * 2);
                const __half2* p0 = reinterpret_cast<const __half2*>(&h0);
                const __half2* p1 = reinterpret_cast<const __half2*>(&h1);
#pragma unroll
                for (int j = 0; j < 4; j++) {
                    float2 f0 = __half22float2(p0[j]);
                    float2 f1 = __half22float2(p1[j]);
                    u0[2*j] = f0.x; u0[2*j+1] = f0.y;
                    u1[2*j] = f1.x; u1[2*j+1] = f1.y;
                }
            }
            float ts9 = tstamp[(size_t)s * DL + (DL - 1)];

            float sc0[DL], sc1[DL];
#pragma unroll
            for (int l = 0; l < DL; l++) {
                if (l >= pad) {
                    float delta = tstamp[(size_t)s * DL + l] - ts9;
                    float a0 = 0.f, a1 = 0.f;
#pragma unroll
                    for (int j = 0; j < 8; j++) {
                        float te = __cosf(fmaf(delta, wt[j], bt[j]));
                        a0 = fmaf(te, u0[j], a0);
                        a1 = fmaf(te, u1[j], a1);
                    }
#pragma unroll
                    for (int o = 16; o; o >>= 1) {
                        a0 += __shfl_xor_sync(0xFFFFFFFF, a0, o);
                        a1 += __shfl_xor_sync(0xFFFFFFFF, a1, o);
                    }
                    sc0[l] = a0 * scale;
                    sc1[l] = a1 * scale;
                } else { sc0[l] = 0.f; sc1[l] = 0.f; }
            }

            float mx0 = -3.4e38f, mx1 = -3.4e38f;
#pragma unroll
            for (int l = 0; l < DL; l++) {
                if (l >= pad) { mx0 = fmaxf(mx0, sc0[l]); mx1 = fmaxf(mx1, sc1[l]); }
            }
            float sm0 = 0.f, sm1 = 0.f;
#pragma unroll
            for (int l = 0; l < DL; l++) {
                if (l >= pad) {
                    sc0[l] = __expf(sc0[l] - mx0); sm0 += sc0[l];
                    sc1[l] = __expf(sc1[l] - mx1); sm1 += sc1[l];
                }
            }
            float i0 = 1.f / sm0, i1 = 1.f / sm1;
#pragma unroll
            for (int l = 0; l < DL; l++) {
                if (l >= pad) { sc0[l] *= i0; sc1[l] *= i1; }
            }

            // aggregate -> Mb (overwrite this sequence's U row; warp-local)
#pragma unroll
            for (int ii = 0; ii < 2; ii++) {
                int e4 = lane * 4 + ii * 128;
                float m0a[4] = {0.f, 0.f, 0.f, 0.f};
                float m1a[4] = {0.f, 0.f, 0.f, 0.f};
                const float* mp = msgs + (size_t)s * DL * DD + e4;
#pragma unroll
                for (int l = 0; l < DL; l++) {
                    if (l >= pad) {
                        float4 v = *reinterpret_cast<const float4*>(mp + (size_t)l * DD);
                        m0a[0] = fmaf(sc0[l], v.x, m0a[0]); m0a[1] = fmaf(sc0[l], v.y, m0a[1]);
                        m0a[2] = fmaf(sc0[l], v.z, m0a[2]); m0a[3] = fmaf(sc0[l], v.w, m0a[3]);
                        m1a[0] = fmaf(sc1[l], v.x, m1a[0]); m1a[1] = fmaf(sc1[l], v.y, m1a[1]);
                        m1a[2] = fmaf(sc1[l], v.z, m1a[2]); m1a[3] = fmaf(sc1[l], v.w, m1a[3]);
                    }
                }
                char* row = sm + (size_t)s_loc * U_PITCH;
                *reinterpret_cast<__half2*>(row + e4 * 2)           = __floats2half2_rn(m0a[0], m0a[1]);
                *reinterpret_cast<__half2*>(row + e4 * 2 + 4)       = __floats2half2_rn(m0a[2], m0a[3]);
                *reinterpret_cast<__half2*>(row + 512 + e4 * 2)     = __floats2half2_rn(m1a[0], m1a[1]);
                *reinterpret_cast<__half2*>(row + 512 + e4 * 2 + 4) = __floats2half2_rn(m1a[2], m1a[3]);
            }
        }
    }

    // ---------- phase 3: OUT = Mb @ Wt^T ----------
    {
        float acc[4][4][4];
#pragma unroll
        for (int a = 0; a < 4; a++)
#pragma unroll
            for (int bq = 0; bq < 4; bq++)
#pragma unroll
                for (int cc = 0; cc < 4; cc++) acc[a][bq][cc] = 0.f;

#pragma unroll 1
        for (int c = 0; c < 16; c++) {
            asm volatile("cp.async.wait_group 1;" ::: "memory");
            __syncthreads();   // c==0: also the phase2 -> phase3 barrier
            if (c + 2 < 16) { P3_LOAD((c + 2) % 3, (c + 2) * 32); }
            else { asm volatile("cp.async.commit_group;" ::: "memory"); }

            const uint32_t uB = uStg + (c % 3) * P3_STG;
#pragma unroll
            for (int kk = 0; kk < 2; kk++) {
                const uint32_t colb = (uint32_t)(kk * 32 + (lane >> 4) * 16);
                const uint32_t ca   = (uint32_t)(c * 64) + colb;
                const uint32_t arow = (uint32_t)(wm + (lane & 15));
                uint32_t af[4][4], bf[2][4];
#pragma unroll
                for (int nt = 0; nt < 2; nt++) {
                    uint32_t brow = (uint32_t)(wn + nt * 16 + (lane & 15));
                    ldsm4(bf[nt], uB + brow * 80 + colb);
                }
#pragma unroll
                for (int mt = 0; mt < 4; mt++)
                    ldsm4(af[mt], uU + (arow + mt * 16) * U_PITCH + ca);
#pragma unroll
                for (int mt = 0; mt < 4; mt++)
#pragma unroll
                    for (int ns = 0; ns < 4; ns++)
                        mma16816(acc[mt][ns], af[mt], bf[ns >> 1][ns & 1], bf[ns >> 1][(ns & 1) + 2]);
            }
        }

        // epilogue to global
#pragma unroll
        for (int mt = 0; mt < 4; mt++) {
            int r0 = m0 + wm + mt * 16 + (lane >> 2);
#pragma unroll
            for (int ns = 0; ns < 4; ns++) {
                int cx = wn + ns * 8 + (lane & 3) * 2;
                float2 bb = *reinterpret_cast<const float2*>(g_bo + cx);
                float2 v0, v1;
                v0.x = acc[mt][ns][0] + bb.x; v0.y = acc[mt][ns][1] + bb.y;
                v1.x = acc[mt][ns][2] + bb.x; v1.y = acc[mt][ns][3] + bb.y;
                *reinterpret_cast<float2*>(out + (size_t)r0 * DD + cx) = v0;
                *reinterpret_cast<float2*>(out + (size_t)(r0 + 8) * DD + cx) = v1;
            }
        }
    }
#undef P1_LOAD
#undef P3_LOAD
}

// ======================= launch =======================

extern "C" void kernel_launch(void* const* d_in, const int* in_sizes, int n_in,
                              void* d_out, int out_size) {
    const float* msgs    = (const float*)d_in[0];
    const float* ts      = (const float*)d_in[1];
    const float* w_time  = (const float*)d_in[2];
    const float* b_time  = (const float*)d_in[3];
    const float* w_in    = (const float*)d_in[4];
    const float* b_in    = (const float*)d_in[5];
    const float* w_out   = (const float*)d_in[6];
    const float* b_out   = (const float*)d_in[7];
    const int*   lengths = (const int*)d_in[8];
    float* out = (float*)d_out;

    cudaFuncSetAttribute(mega, cudaFuncAttributeMaxDynamicSharedMemorySize, MEGA_SMEM);

    prep<<<4483, 256>>>(w_in, b_in, w_out, b_out, msgs);
    mega<<<128, 512, MEGA_SMEM>>>(msgs, ts, w_time, b_time, lengths, out);
}